// round 11
// baseline (speedup 1.0000x reference)
#include <cuda_runtime.h>
#include <math.h>

#define TT    1000
#define BB    128
#define NIN   85
#define NRNN  512
#define NOUT  33
#define MM    (TT * BB)     /* 128000 rows */
#define STEP  (BB * NRNN)   /* 65536 */
#define PF    8             /* G prefetch ring depth in diag recurrence */

typedef unsigned long long u64;

// ---------------------------------------------------------------------------
// Packed f32x2 helpers (exact IEEE fp32 per lane; 2x FFMA rate on sm_103a)
// ---------------------------------------------------------------------------
__device__ __forceinline__ u64 pack2(float lo, float hi) {
    u64 r; asm("mov.b64 %0, {%1, %2};" : "=l"(r) : "f"(lo), "f"(hi)); return r;
}
__device__ __forceinline__ void unpack2(u64 v, float& lo, float& hi) {
    asm("mov.b64 {%0, %1}, %2;" : "=f"(lo), "=f"(hi) : "l"(v));
}
__device__ __forceinline__ u64 fma2(u64 a, u64 b, u64 c) {
    u64 d; asm("fma.rn.f32x2 %0, %1, %2, %3;" : "=l"(d) : "l"(a), "l"(b), "l"(c));
    return d;
}

// ---------------------------------------------------------------------------
// Scratch (__device__ globals: module-load allocated, no runtime alloc)
// ---------------------------------------------------------------------------
__device__ float g_G[(size_t)TT * BB * NRNN];      // pre-gate, 262 MB
__device__ float g_xT[(size_t)NIN * MM];           // transposed x, 43.5 MB
__device__ int   g_cnt[NRNN];                      // sparse W_rec (fallback only)
__device__ int   g_idx[NRNN * NRNN];
__device__ float g_val[NRNN * NRNN];
__device__ int   g_diag;                           // 1 iff W_rec is diagonal
__device__ float g_wdiag[NRNN];                    // diagonal weight per column

__global__ void init_kernel() { g_diag = 1; }

// Parallel diagonal detection (coalesced in n); atomicAnd fires only on
// nonzero off-diagonals. Skipping exact zeros is bit-exact in fp32.
__global__ void detect_diag(const float* __restrict__ W) {
    int e = blockIdx.x * blockDim.x + threadIdx.x;   // 262144 threads
    int k = e >> 9;
    int n = e & (NRNN - 1);
    float w = W[(size_t)(NIN + k) * NRNN + n];
    if (k == n)          g_wdiag[n] = w;
    else if (w != 0.0f)  atomicAnd(&g_diag, 0);
}

// CSC build — only runs on non-diagonal inputs (predicated on !g_diag).
__global__ void build_csc(const float* __restrict__ W) {
    if (g_diag) return;
    if (threadIdx.x != 0) return;
    int n = blockIdx.x;
    int c = 0;
    for (int k = 0; k < NRNN; k++) {
        float w = W[(size_t)(NIN + k) * NRNN + n];
        if (w != 0.0f) {
            g_idx[n * NRNN + c] = k;
            g_val[n * NRNN + c] = w;
            c++;
        }
    }
    g_cnt[n] = c;
}

// ---------------------------------------------------------------------------
// Kernel 0d: global transpose x[M,85] -> xT[85,M]. Shared 32x32 tile.
// ---------------------------------------------------------------------------
__global__ void transpose_x(const float* __restrict__ x) {
    __shared__ float tile[32][33];
    int mb = blockIdx.x * 32;
    int kb = blockIdx.y * 32;
    int tx = threadIdx.x;                // 32
    int ty = threadIdx.y;                // 8
    #pragma unroll
    for (int i = ty; i < 32; i += 8) {
        int k = kb + tx;
        tile[i][tx] = (k < NIN) ? x[(size_t)(mb + i) * NIN + k] : 0.0f;
    }
    __syncthreads();
    #pragma unroll
    for (int i = ty; i < 32; i += 8) {
        int k = kb + i;
        if (k < NIN) g_xT[(size_t)k * MM + mb + tx] = tile[tx][i];
    }
}

// ---------------------------------------------------------------------------
// Kernel 1: G[m,n] = x[m,:] @ W_in[:,n] + b[n] + noise[m,n]
// M=128000, K=85, N=512. CTA tile 128x64, 256 threads, 4 rows x 8 cols
// per thread (2 row-pairs). launch_bounds(256,3): 24 warps/SM (was 16) for
// latency coverage. Inner loop per k: 5 LDS.128 + 16 FFMA2, zero MOVs,
// all conflict-free (a: 64B span broadcast; w: tx*16B spans 128B).
// ---------------------------------------------------------------------------
#define TM 128
#define TN 64
#define KT 32
__global__ void __launch_bounds__(256, 3) phase1_kernel(
        const float* __restrict__ W,
        const float* __restrict__ bias,
        const float* __restrict__ noise) {
    __shared__ u64 As2[KT][TM / 2];      // row-pair a: 16.4 KB
    __shared__ u64 Wsb[KT][TN];          // broadcast-packed w: 16.4 KB

    int tid = threadIdx.x;               // 256 threads
    int m0  = blockIdx.x * TM;           // 1000 M-tiles
    int n0  = blockIdx.y * TN;           // 8 N-tiles
    int tx  = tid & 7;                   // col lane: cols g*16 + tx*2 + {0,1}
    int ty  = tid >> 3;                  // row group: rows ty*4..ty*4+3 (2 pairs)

    u64 acc[2][8] = {};                  // [row-pair][g*2 + d]

    for (int k0 = 0; k0 < NIN; k0 += KT) {
        int kmax = NIN - k0; if (kmax > KT) kmax = KT;
        __syncthreads();
        // stage a: fixed k, consecutive float4 of m. LDG.128 coalesced,
        // STS.128 consecutive: conflict-free. Row pairs form naturally.
        for (int idx = tid; idx < KT * (TM / 4); idx += 256) {
            int k  = idx >> 5;           // TM/4 = 32
            int r4 = idx & 31;
            float4 v;
            if (k < kmax)
                v = *reinterpret_cast<const float4*>(
                        &g_xT[(size_t)(k0 + k) * MM + m0 + r4 * 4]);
            else
                v = make_float4(0.f, 0.f, 0.f, 0.f);
            *reinterpret_cast<float4*>(&As2[k][r4 * 2]) = v;
        }
        // stage w broadcast-packed: coalesced LDG, consecutive STS.64
        for (int idx = tid; idx < KT * TN; idx += 256) {
            int k = idx >> 6;
            int n = idx & 63;
            float w = (k < kmax) ? W[(size_t)(k0 + k) * NRNN + n0 + n] : 0.0f;
            Wsb[k][n] = pack2(w, w);
        }
        __syncthreads();

        #pragma unroll 4
        for (int k = 0; k < kmax; k++) {
            // a: pairs (2ty, 2ty+1) = rows ty*4..ty*4+3, one LDS.128
            ulonglong2 a = *reinterpret_cast<ulonglong2*>(&As2[k][ty * 2]);
            #pragma unroll
            for (int g = 0; g < 4; g++) {
                ulonglong2 w = *reinterpret_cast<ulonglong2*>(
                    &Wsb[k][g * 16 + tx * 2]);
                acc[0][g*2]   = fma2(a.x, w.x, acc[0][g*2]);
                acc[0][g*2+1] = fma2(a.x, w.y, acc[0][g*2+1]);
                acc[1][g*2]   = fma2(a.y, w.x, acc[1][g*2]);
                acc[1][g*2+1] = fma2(a.y, w.y, acc[1][g*2+1]);
            }
        }
    }

    // epilogue: acc[p][g*2+d] = rows (m, m+1) x column g*16 + tx*2 + d
    float2 bb[4];
    #pragma unroll
    for (int g = 0; g < 4; g++)
        bb[g] = *reinterpret_cast<const float2*>(&bias[n0 + g * 16 + tx * 2]);

    #pragma unroll
    for (int p = 0; p < 2; p++) {
        int m = m0 + ty * 4 + p * 2;
        size_t row0 = (size_t)m * NRNN + n0;
        size_t row1 = row0 + NRNN;
        #pragma unroll
        for (int g = 0; g < 4; g++) {
            int c = g * 16 + tx * 2;
            float l0, h0, l1, h1;
            unpack2(acc[p][g*2],   l0, h0);   // (row m, row m+1) col c
            unpack2(acc[p][g*2+1], l1, h1);   // (row m, row m+1) col c+1
            float2 nz0 = *reinterpret_cast<const float2*>(&noise[row0 + c]);
            float2 nz1 = *reinterpret_cast<const float2*>(&noise[row1 + c]);
            float2 o0, o1;
            o0.x = l0 + bb[g].x + nz0.x;
            o0.y = l1 + bb[g].y + nz0.y;
            o1.x = h0 + bb[g].x + nz1.x;
            o1.y = h1 + bb[g].y + nz1.y;
            *reinterpret_cast<float2*>(&g_G[row0 + c]) = o0;
            *reinterpret_cast<float2*>(&g_G[row1 + c]) = o1;
        }
    }
}

// ---------------------------------------------------------------------------
// Kernel 2a (fast path): pure-diagonal recurrence. Independent chains,
// h in a register, no barriers, depth-PF G prefetch ring.
// ---------------------------------------------------------------------------
__global__ void rec_diag_kernel(float* __restrict__ Hout) {
    if (!g_diag) return;
    int e = blockIdx.x * blockDim.x + threadIdx.x;   // 65536 threads
    int n = e & (NRNN - 1);
    float w = g_wdiag[n];

    const float* Gp = g_G + e;
    float*       Hp = Hout + e;

    float buf[PF];
    #pragma unroll
    for (int i = 0; i < PF; i++) buf[i] = Gp[(size_t)i * STEP];

    float h = 0.0f;
    for (int t0 = 0; t0 < TT; t0 += PF) {
        #pragma unroll
        for (int i = 0; i < PF; i++) {
            int t = t0 + i;
            float g = buf[i];
            int tf = t + PF;
            if (tf < TT) buf[i] = Gp[(size_t)tf * STEP];
            float acc = fmaf(w, h, g);
            float sp  = fmaxf(acc, 0.0f) + __logf(1.0f + __expf(-fabsf(acc)));
            h = 0.8f * h + 0.2f * sp;
            Hp[(size_t)t * STEP] = h;
        }
    }
}

// ---------------------------------------------------------------------------
// Kernel 2b (generic fallback): barriered sparse recurrence, one CTA/batch.
// ---------------------------------------------------------------------------
__global__ void rec_generic_kernel(float* __restrict__ Hout) {
    if (g_diag) return;
    __shared__ float hs[2][NRNN];
    int n = threadIdx.x;
    int b = blockIdx.x;

    hs[0][n] = 0.0f;

    int cnt = g_cnt[n];
    int   ki[4];
    float wv[4];
    #pragma unroll
    for (int j = 0; j < 4; j++) {
        if (j < cnt) { ki[j] = g_idx[n * NRNN + j]; wv[j] = g_val[n * NRNN + j]; }
        else         { ki[j] = 0;                    wv[j] = 0.0f; }
    }

    const float* Gb = g_G + (size_t)b * NRNN + n;
    float*       Hb = Hout + (size_t)b * NRNN + n;
    __syncthreads();

    int p = 0;
    float gcur = Gb[0];
    for (int t = 0; t < TT; t++) {
        int tn = (t + 1 < TT) ? (t + 1) : t;
        float gnext = Gb[(size_t)tn * STEP];

        float acc = gcur;
        acc = fmaf(wv[0], hs[p][ki[0]], acc);
        acc = fmaf(wv[1], hs[p][ki[1]], acc);
        acc = fmaf(wv[2], hs[p][ki[2]], acc);
        acc = fmaf(wv[3], hs[p][ki[3]], acc);
        for (int j = 4; j < cnt; j++)
            acc = fmaf(g_val[n * NRNN + j], hs[p][g_idx[n * NRNN + j]], acc);

        float sp = fmaxf(acc, 0.0f) + __logf(1.0f + __expf(-fabsf(acc)));
        float hn = 0.8f * hs[p][n] + 0.2f * sp;

        hs[p ^ 1][n] = hn;
        Hb[(size_t)t * STEP] = hn;
        __syncthreads();
        p ^= 1;
        gcur = gnext;
    }
}

// ---------------------------------------------------------------------------
// Kernel 3: y[m,o] = sigmoid(h[m,:] @ W_out[:,o] + b_out[o])
// o2-split groups x 4 interleaved rows/thread; conflict-free stride-9 LDS.
// ---------------------------------------------------------------------------
#define P3BK 8
#define P3PAD (P3BK + 1)
#define NO2  17
#define NO2G 9
__global__ void __launch_bounds__(256) phase3_kernel(
        const float* __restrict__ Hin,
        const float* __restrict__ Wout,
        const float* __restrict__ bout,
        float* __restrict__ y) {
    __shared__ float hsh[512][P3PAD];
    __shared__ u64   wsh2[P3BK][NO2];

    int tid = threadIdx.x;                        // 256 threads
    int g   = tid >> 7;
    int t   = tid & 127;
    int m0  = blockIdx.x * 512;                   // 250 blocks
    int ob  = g * NO2G;

    u64 acc[4][NO2G] = {};

    for (int k0 = 0; k0 < NRNN; k0 += P3BK) {
        __syncthreads();
        for (int idx = tid; idx < 512 * P3BK; idx += 256) {
            int r = idx >> 3;
            int k = idx & (P3BK - 1);
            hsh[r][k] = Hin[(size_t)(m0 + r) * NRNN + k0 + k];
        }
        for (int idx = tid; idx < P3BK * NO2; idx += 256) {
            int k  = idx / NO2;
            int o2 = idx - k * NO2;
            float lo = Wout[(size_t)(k0 + k) * NOUT + 2 * o2];
            float hi = (2 * o2 + 1 < NOUT) ? Wout[(size_t)(k0 + k) * NOUT + 2 * o2 + 1] : 0.0f;
            wsh2[k][o2] = pack2(lo, hi);
        }
        __syncthreads();

        #pragma unroll
        for (int kk = 0; kk < P3BK; kk++) {
            u64 hp[4];
            #pragma unroll
            for (int i = 0; i < 4; i++) {
                float hv = hsh[t + i * 128][kk];
                hp[i] = pack2(hv, hv);
            }
            #pragma unroll
            for (int j = 0; j < NO2G; j++) {
                int o2 = ob + j;
                u64 w = (o2 < NO2) ? wsh2[kk][o2] : 0ull;
                #pragma unroll
                for (int i = 0; i < 4; i++)
                    acc[i][j] = fma2(hp[i], w, acc[i][j]);
            }
        }
    }

    #pragma unroll
    for (int j = 0; j < NO2G; j++) {
        int o2 = ob + j;
        if (o2 >= NO2) continue;
        float b0 = bout[2 * o2];
        float b1 = (2 * o2 + 1 < NOUT) ? bout[2 * o2 + 1] : 0.0f;
        #pragma unroll
        for (int i = 0; i < 4; i++) {
            int r = m0 + t + i * 128;
            float v0, v1;
            unpack2(acc[i][j], v0, v1);
            y[(size_t)r * NOUT + 2 * o2] = 1.0f / (1.0f + __expf(-(v0 + b0)));
            if (2 * o2 + 1 < NOUT)
                y[(size_t)r * NOUT + 2 * o2 + 1] = 1.0f / (1.0f + __expf(-(v1 + b1)));
        }
    }
}

// ---------------------------------------------------------------------------
// Launch. Inputs: x, W, b, W_out, b_out, noise.
// Output: [y_hat (T*B*33) | h (T*B*512)] fp32.
// ---------------------------------------------------------------------------
extern "C" void kernel_launch(void* const* d_in, const int* in_sizes, int n_in,
                              void* d_out, int out_size) {
    const float* x     = (const float*)d_in[0];
    const float* W     = (const float*)d_in[1];
    const float* b     = (const float*)d_in[2];
    const float* W_out = (const float*)d_in[3];
    const float* b_out = (const float*)d_in[4];
    const float* noise = (const float*)d_in[5];

    float* y = (float*)d_out;
    float* h = (float*)d_out + (size_t)TT * BB * NOUT;

    init_kernel<<<1, 1>>>();
    detect_diag<<<(NRNN * NRNN) / 256, 256>>>(W);
    build_csc<<<NRNN, 32>>>(W);                              // fallback only
    transpose_x<<<dim3(MM / 32, (NIN + 31) / 32), dim3(32, 8)>>>(x);
    phase1_kernel<<<dim3(MM / TM, NRNN / TN), 256>>>(W, b, noise);
    rec_diag_kernel<<<(BB * NRNN) / 256, 256>>>(h);          // fast path
    rec_generic_kernel<<<BB, NRNN>>>(h);                     // fallback
    phase3_kernel<<<(TT * BB) / 512, 256>>>(h, W_out, b_out, y);
}

// round 12
// speedup vs baseline: 1.2699x; 1.2699x over previous
#include <cuda_runtime.h>
#include <math.h>

#define TT    1000
#define BB    128
#define NIN   85
#define NRNN  512
#define NOUT  33
#define MM    (TT * BB)     /* 128000 rows */
#define STEP  (BB * NRNN)   /* 65536 */
#define PF    8             /* G prefetch ring depth in diag recurrence */

typedef unsigned long long u64;

// ---------------------------------------------------------------------------
// Packed f32x2 helpers (exact IEEE fp32 per lane; 2x FFMA rate on sm_103a)
// ---------------------------------------------------------------------------
__device__ __forceinline__ u64 pack2(float lo, float hi) {
    u64 r; asm("mov.b64 %0, {%1, %2};" : "=l"(r) : "f"(lo), "f"(hi)); return r;
}
__device__ __forceinline__ void unpack2(u64 v, float& lo, float& hi) {
    asm("mov.b64 {%0, %1}, %2;" : "=f"(lo), "=f"(hi) : "l"(v));
}
__device__ __forceinline__ u64 fma2(u64 a, u64 b, u64 c) {
    u64 d; asm("fma.rn.f32x2 %0, %1, %2, %3;" : "=l"(d) : "l"(a), "l"(b), "l"(c));
    return d;
}
__device__ __forceinline__ unsigned s2u(const void* p) {
    return (unsigned)__cvta_generic_to_shared(p);
}
__device__ __forceinline__ void cp16(unsigned s, const void* g) {
    asm volatile("cp.async.cg.shared.global [%0], [%1], 16;" :: "r"(s), "l"(g));
}

// ---------------------------------------------------------------------------
// Scratch (__device__ globals: module-load allocated, no runtime alloc)
// ---------------------------------------------------------------------------
__device__ float g_G[(size_t)TT * BB * NRNN];      // pre-gate, 262 MB
__device__ float g_xT[(size_t)NIN * MM];           // transposed x, 43.5 MB
__device__ u64   g_Wpk[(size_t)NIN * NRNN];        // (w,w)-packed W_in, 348 KB
__device__ int   g_cnt[NRNN];                      // sparse W_rec (fallback only)
__device__ int   g_idx[NRNN * NRNN];
__device__ float g_val[NRNN * NRNN];
__device__ int   g_diag;                           // 1 iff W_rec is diagonal
__device__ float g_wdiag[NRNN];                    // diagonal weight per column

__global__ void init_kernel() { g_diag = 1; }

// Parallel diagonal detection (coalesced in n); atomicAnd fires only on
// nonzero off-diagonals. Skipping exact zeros is bit-exact in fp32.
__global__ void detect_diag(const float* __restrict__ W) {
    int e = blockIdx.x * blockDim.x + threadIdx.x;   // 262144 threads
    int k = e >> 9;
    int n = e & (NRNN - 1);
    float w = W[(size_t)(NIN + k) * NRNN + n];
    if (k == n)          g_wdiag[n] = w;
    else if (w != 0.0f)  atomicAnd(&g_diag, 0);
}

// CSC build — only runs on non-diagonal inputs (predicated on !g_diag).
__global__ void build_csc(const float* __restrict__ W) {
    if (g_diag) return;
    if (threadIdx.x != 0) return;
    int n = blockIdx.x;
    int c = 0;
    for (int k = 0; k < NRNN; k++) {
        float w = W[(size_t)(NIN + k) * NRNN + n];
        if (w != 0.0f) {
            g_idx[n * NRNN + c] = k;
            g_val[n * NRNN + c] = w;
            c++;
        }
    }
    g_cnt[n] = c;
}

// Pre-pack W_in as (w,w) u64 so phase1 w-staging is a raw 16B copy (cp.async).
__global__ void pack_w(const float* __restrict__ W) {
    int i = blockIdx.x * blockDim.x + threadIdx.x;
    if (i < NIN * NRNN) { float w = W[i]; g_Wpk[i] = pack2(w, w); }
}

// ---------------------------------------------------------------------------
// Kernel 0d: global transpose x[M,85] -> xT[85,M]. Shared 32x32 tile.
// ---------------------------------------------------------------------------
__global__ void transpose_x(const float* __restrict__ x) {
    __shared__ float tile[32][33];
    int mb = blockIdx.x * 32;
    int kb = blockIdx.y * 32;
    int tx = threadIdx.x;                // 32
    int ty = threadIdx.y;                // 8
    #pragma unroll
    for (int i = ty; i < 32; i += 8) {
        int k = kb + tx;
        tile[i][tx] = (k < NIN) ? x[(size_t)(mb + i) * NIN + k] : 0.0f;
    }
    __syncthreads();
    #pragma unroll
    for (int i = ty; i < 32; i += 8) {
        int k = kb + i;
        if (k < NIN) g_xT[(size_t)k * MM + mb + tx] = tile[tx][i];
    }
}

// ---------------------------------------------------------------------------
// Kernel 1: G[m,n] = x[m,:] @ W_in[:,n] + b[n] + noise[m,n]
// R10's proven inner loop (128 thr, 8 rows x 8 cols, zero MOVs, conflict-
// free) + cp.async DOUBLE-BUFFERED staging: KT=17 (85=5x17), both tiles are
// raw 16B copies (a from xT, w from pre-packed Wpk). Staging latency hidden
// behind 1088 fma-cycles/warp/tile. (128,4): 16 warps/SM, smem 34.8 KB.
// ---------------------------------------------------------------------------
#define TM 128
#define TN 64
#define KT 17
#define NTILES 5
__global__ void __launch_bounds__(128, 4) phase1_kernel(
        const float* __restrict__ bias,
        const float* __restrict__ noise) {
    __shared__ u64 As2[2][KT][TM / 2];   // row-pair a: 2 x 8.7 KB
    __shared__ u64 Wsb[2][KT][TN];       // packed w:   2 x 8.7 KB

    int tid = threadIdx.x;               // 128 threads
    int m0  = blockIdx.x * TM;           // 1000 M-tiles
    int n0  = blockIdx.y * TN;           // 8 N-tiles
    int tx  = tid & 7;                   // col lane
    int ty  = tid >> 3;                  // row group (4 pairs)

    u64 acc[4][8] = {};

    // stage tile (k0..k0+16) into buffer buf: 2x 544 cp.async.16 per CTA
    auto stage = [&](int buf, int k0) {
        for (int idx = tid; idx < KT * 32; idx += 128) {
            int k = idx >> 5;
            int c = idx & 31;
            cp16(s2u(&As2[buf][k][c * 2]),
                 &g_xT[(size_t)(k0 + k) * MM + m0 + c * 4]);
        }
        for (int idx = tid; idx < KT * 32; idx += 128) {
            int k = idx >> 5;
            int c = idx & 31;
            cp16(s2u(&Wsb[buf][k][c * 2]),
                 &g_Wpk[(size_t)(k0 + k) * NRNN + n0 + c * 2]);
        }
        asm volatile("cp.async.commit_group;" ::: "memory");
    };

    stage(0, 0);
    stage(1, KT);

    #pragma unroll 1
    for (int t = 0; t < NTILES; t++) {
        if (t + 1 < NTILES)
            asm volatile("cp.async.wait_group 1;" ::: "memory");
        else
            asm volatile("cp.async.wait_group 0;" ::: "memory");
        __syncthreads();

        int buf = t & 1;
        #pragma unroll
        for (int k = 0; k < KT; k++) {
            ulonglong2 a01 = *reinterpret_cast<ulonglong2*>(&As2[buf][k][ty * 4]);
            ulonglong2 a23 = *reinterpret_cast<ulonglong2*>(&As2[buf][k][ty * 4 + 2]);
            #pragma unroll
            for (int g = 0; g < 4; g++) {
                ulonglong2 w = *reinterpret_cast<ulonglong2*>(
                    &Wsb[buf][k][g * 16 + tx * 2]);
                acc[0][g*2]   = fma2(a01.x, w.x, acc[0][g*2]);
                acc[0][g*2+1] = fma2(a01.x, w.y, acc[0][g*2+1]);
                acc[1][g*2]   = fma2(a01.y, w.x, acc[1][g*2]);
                acc[1][g*2+1] = fma2(a01.y, w.y, acc[1][g*2+1]);
                acc[2][g*2]   = fma2(a23.x, w.x, acc[2][g*2]);
                acc[2][g*2+1] = fma2(a23.x, w.y, acc[2][g*2+1]);
                acc[3][g*2]   = fma2(a23.y, w.x, acc[3][g*2]);
                acc[3][g*2+1] = fma2(a23.y, w.y, acc[3][g*2+1]);
            }
        }
        __syncthreads();
        if (t + 2 < NTILES) stage(buf, (t + 2) * KT);
    }

    // epilogue: acc[p][g*2+d] = rows (m, m+1) x column g*16 + tx*2 + d
    float2 bb[4];
    #pragma unroll
    for (int g = 0; g < 4; g++)
        bb[g] = *reinterpret_cast<const float2*>(&bias[n0 + g * 16 + tx * 2]);

    #pragma unroll
    for (int p = 0; p < 4; p++) {
        int m = m0 + ty * 8 + p * 2;
        size_t row0 = (size_t)m * NRNN + n0;
        size_t row1 = row0 + NRNN;
        #pragma unroll
        for (int g = 0; g < 4; g++) {
            int c = g * 16 + tx * 2;
            float l0, h0, l1, h1;
            unpack2(acc[p][g*2],   l0, h0);
            unpack2(acc[p][g*2+1], l1, h1);
            float2 nz0 = *reinterpret_cast<const float2*>(&noise[row0 + c]);
            float2 nz1 = *reinterpret_cast<const float2*>(&noise[row1 + c]);
            float2 o0, o1;
            o0.x = l0 + bb[g].x + nz0.x;
            o0.y = l1 + bb[g].y + nz0.y;
            o1.x = h0 + bb[g].x + nz1.x;
            o1.y = h1 + bb[g].y + nz1.y;
            *reinterpret_cast<float2*>(&g_G[row0 + c]) = o0;
            *reinterpret_cast<float2*>(&g_G[row1 + c]) = o1;
        }
    }
}

// ---------------------------------------------------------------------------
// Kernel 2a (fast path): pure-diagonal recurrence. Independent chains,
// h in a register, no barriers, depth-PF G prefetch ring.
// ---------------------------------------------------------------------------
__global__ void rec_diag_kernel(float* __restrict__ Hout) {
    if (!g_diag) return;
    int e = blockIdx.x * blockDim.x + threadIdx.x;   // 65536 threads
    int n = e & (NRNN - 1);
    float w = g_wdiag[n];

    const float* Gp = g_G + e;
    float*       Hp = Hout + e;

    float buf[PF];
    #pragma unroll
    for (int i = 0; i < PF; i++) buf[i] = Gp[(size_t)i * STEP];

    float h = 0.0f;
    for (int t0 = 0; t0 < TT; t0 += PF) {
        #pragma unroll
        for (int i = 0; i < PF; i++) {
            int t = t0 + i;
            float g = buf[i];
            int tf = t + PF;
            if (tf < TT) buf[i] = Gp[(size_t)tf * STEP];
            float acc = fmaf(w, h, g);
            float sp  = fmaxf(acc, 0.0f) + __logf(1.0f + __expf(-fabsf(acc)));
            h = 0.8f * h + 0.2f * sp;
            Hp[(size_t)t * STEP] = h;
        }
    }
}

// ---------------------------------------------------------------------------
// Kernel 2b (generic fallback): barriered sparse recurrence, one CTA/batch.
// ---------------------------------------------------------------------------
__global__ void rec_generic_kernel(float* __restrict__ Hout) {
    if (g_diag) return;
    __shared__ float hs[2][NRNN];
    int n = threadIdx.x;
    int b = blockIdx.x;

    hs[0][n] = 0.0f;

    int cnt = g_cnt[n];
    int   ki[4];
    float wv[4];
    #pragma unroll
    for (int j = 0; j < 4; j++) {
        if (j < cnt) { ki[j] = g_idx[n * NRNN + j]; wv[j] = g_val[n * NRNN + j]; }
        else         { ki[j] = 0;                    wv[j] = 0.0f; }
    }

    const float* Gb = g_G + (size_t)b * NRNN + n;
    float*       Hb = Hout + (size_t)b * NRNN + n;
    __syncthreads();

    int p = 0;
    float gcur = Gb[0];
    for (int t = 0; t < TT; t++) {
        int tn = (t + 1 < TT) ? (t + 1) : t;
        float gnext = Gb[(size_t)tn * STEP];

        float acc = gcur;
        acc = fmaf(wv[0], hs[p][ki[0]], acc);
        acc = fmaf(wv[1], hs[p][ki[1]], acc);
        acc = fmaf(wv[2], hs[p][ki[2]], acc);
        acc = fmaf(wv[3], hs[p][ki[3]], acc);
        for (int j = 4; j < cnt; j++)
            acc = fmaf(g_val[n * NRNN + j], hs[p][g_idx[n * NRNN + j]], acc);

        float sp = fmaxf(acc, 0.0f) + __logf(1.0f + __expf(-fabsf(acc)));
        float hn = 0.8f * hs[p][n] + 0.2f * sp;

        hs[p ^ 1][n] = hn;
        Hb[(size_t)t * STEP] = hn;
        __syncthreads();
        p ^= 1;
        gcur = gnext;
    }
}

// ---------------------------------------------------------------------------
// Kernel 3: y[m,o] = sigmoid(h[m,:] @ W_out[:,o] + b_out[o])
// o2-split groups x 4 interleaved rows/thread; conflict-free stride-9 LDS.
// ---------------------------------------------------------------------------
#define P3BK 8
#define P3PAD (P3BK + 1)
#define NO2  17
#define NO2G 9
__global__ void __launch_bounds__(256) phase3_kernel(
        const float* __restrict__ Hin,
        const float* __restrict__ Wout,
        const float* __restrict__ bout,
        float* __restrict__ y) {
    __shared__ float hsh[512][P3PAD];
    __shared__ u64   wsh2[P3BK][NO2];

    int tid = threadIdx.x;                        // 256 threads
    int g   = tid >> 7;
    int t   = tid & 127;
    int m0  = blockIdx.x * 512;                   // 250 blocks
    int ob  = g * NO2G;

    u64 acc[4][NO2G] = {};

    for (int k0 = 0; k0 < NRNN; k0 += P3BK) {
        __syncthreads();
        for (int idx = tid; idx < 512 * P3BK; idx += 256) {
            int r = idx >> 3;
            int k = idx & (P3BK - 1);
            hsh[r][k] = Hin[(size_t)(m0 + r) * NRNN + k0 + k];
        }
        for (int idx = tid; idx < P3BK * NO2; idx += 256) {
            int k  = idx / NO2;
            int o2 = idx - k * NO2;
            float lo = Wout[(size_t)(k0 + k) * NOUT + 2 * o2];
            float hi = (2 * o2 + 1 < NOUT) ? Wout[(size_t)(k0 + k) * NOUT + 2 * o2 + 1] : 0.0f;
            wsh2[k][o2] = pack2(lo, hi);
        }
        __syncthreads();

        #pragma unroll
        for (int kk = 0; kk < P3BK; kk++) {
            u64 hp[4];
            #pragma unroll
            for (int i = 0; i < 4; i++) {
                float hv = hsh[t + i * 128][kk];
                hp[i] = pack2(hv, hv);
            }
            #pragma unroll
            for (int j = 0; j < NO2G; j++) {
                int o2 = ob + j;
                u64 w = (o2 < NO2) ? wsh2[kk][o2] : 0ull;
                #pragma unroll
                for (int i = 0; i < 4; i++)
                    acc[i][j] = fma2(hp[i], w, acc[i][j]);
            }
        }
    }

    #pragma unroll
    for (int j = 0; j < NO2G; j++) {
        int o2 = ob + j;
        if (o2 >= NO2) continue;
        float b0 = bout[2 * o2];
        float b1 = (2 * o2 + 1 < NOUT) ? bout[2 * o2 + 1] : 0.0f;
        #pragma unroll
        for (int i = 0; i < 4; i++) {
            int r = m0 + t + i * 128;
            float v0, v1;
            unpack2(acc[i][j], v0, v1);
            y[(size_t)r * NOUT + 2 * o2] = 1.0f / (1.0f + __expf(-(v0 + b0)));
            if (2 * o2 + 1 < NOUT)
                y[(size_t)r * NOUT + 2 * o2 + 1] = 1.0f / (1.0f + __expf(-(v1 + b1)));
        }
    }
}

// ---------------------------------------------------------------------------
// Launch. Inputs: x, W, b, W_out, b_out, noise.
// Output: [y_hat (T*B*33) | h (T*B*512)] fp32.
// ---------------------------------------------------------------------------
extern "C" void kernel_launch(void* const* d_in, const int* in_sizes, int n_in,
                              void* d_out, int out_size) {
    const float* x     = (const float*)d_in[0];
    const float* W     = (const float*)d_in[1];
    const float* b     = (const float*)d_in[2];
    const float* W_out = (const float*)d_in[3];
    const float* b_out = (const float*)d_in[4];
    const float* noise = (const float*)d_in[5];

    float* y = (float*)d_out;
    float* h = (float*)d_out + (size_t)TT * BB * NOUT;

    init_kernel<<<1, 1>>>();
    detect_diag<<<(NRNN * NRNN) / 256, 256>>>(W);
    build_csc<<<NRNN, 32>>>(W);                              // fallback only
    pack_w<<<(NIN * NRNN + 255) / 256, 256>>>(W);
    transpose_x<<<dim3(MM / 32, (NIN + 31) / 32), dim3(32, 8)>>>(x);
    phase1_kernel<<<dim3(MM / TM, NRNN / TN), 128>>>(b, noise);
    rec_diag_kernel<<<(BB * NRNN) / 256, 256>>>(h);          // fast path
    rec_generic_kernel<<<BB, NRNN>>>(h);                     // fallback
    phase3_kernel<<<(TT * BB) / 512, 256>>>(h, W_out, b_out, y);
}

// round 13
// speedup vs baseline: 1.3803x; 1.0869x over previous
#include <cuda_runtime.h>
#include <math.h>

#define TT    1000
#define BB    128
#define NIN   85
#define NRNN  512
#define NOUT  33
#define MM    (TT * BB)     /* 128000 rows */
#define STEP  (BB * NRNN)   /* 65536 */
#define PF    8             /* G prefetch ring depth in diag recurrence */

typedef unsigned long long u64;

// ---------------------------------------------------------------------------
// Packed f32x2 helpers (exact IEEE fp32 per lane; 2x FFMA rate on sm_103a)
// ---------------------------------------------------------------------------
__device__ __forceinline__ u64 pack2(float lo, float hi) {
    u64 r; asm("mov.b64 %0, {%1, %2};" : "=l"(r) : "f"(lo), "f"(hi)); return r;
}
__device__ __forceinline__ void unpack2(u64 v, float& lo, float& hi) {
    asm("mov.b64 {%0, %1}, %2;" : "=f"(lo), "=f"(hi) : "l"(v));
}
__device__ __forceinline__ u64 fma2(u64 a, u64 b, u64 c) {
    u64 d; asm("fma.rn.f32x2 %0, %1, %2, %3;" : "=l"(d) : "l"(a), "l"(b), "l"(c));
    return d;
}
__device__ __forceinline__ unsigned s2u(const void* p) {
    return (unsigned)__cvta_generic_to_shared(p);
}
__device__ __forceinline__ void cp16(unsigned s, const void* g) {
    asm volatile("cp.async.cg.shared.global [%0], [%1], 16;" :: "r"(s), "l"(g));
}

// ---------------------------------------------------------------------------
// Scratch (__device__ globals: module-load allocated, no runtime alloc)
// ---------------------------------------------------------------------------
__device__ float g_G[(size_t)TT * BB * NRNN];      // pre-gate, 262 MB
__device__ float g_xT[(size_t)NIN * MM];           // transposed x, 43.5 MB
__device__ __align__(16) u64 g_Wpk[(size_t)NIN * NRNN];     // (w,w) W_in
__device__ __align__(16) u64 g_WoPk[(size_t)NRNN * 18];     // (lo,hi) W_out pairs
__device__ int   g_cnt[NRNN];                      // sparse W_rec (fallback only)
__device__ int   g_idx[NRNN * NRNN];
__device__ float g_val[NRNN * NRNN];
__device__ int   g_diag;                           // 1 iff W_rec is diagonal
__device__ float g_wdiag[NRNN];                    // diagonal weight per column

__global__ void init_kernel() { g_diag = 1; }

// Parallel diagonal detection (coalesced in n); atomicAnd fires only on
// nonzero off-diagonals. Skipping exact zeros is bit-exact in fp32.
__global__ void detect_diag(const float* __restrict__ W) {
    int e = blockIdx.x * blockDim.x + threadIdx.x;   // 262144 threads
    int k = e >> 9;
    int n = e & (NRNN - 1);
    float w = W[(size_t)(NIN + k) * NRNN + n];
    if (k == n)          g_wdiag[n] = w;
    else if (w != 0.0f)  atomicAnd(&g_diag, 0);
}

// CSC build — only runs on non-diagonal inputs (predicated on !g_diag).
__global__ void build_csc(const float* __restrict__ W) {
    if (g_diag) return;
    if (threadIdx.x != 0) return;
    int n = blockIdx.x;
    int c = 0;
    for (int k = 0; k < NRNN; k++) {
        float w = W[(size_t)(NIN + k) * NRNN + n];
        if (w != 0.0f) {
            g_idx[n * NRNN + c] = k;
            g_val[n * NRNN + c] = w;
            c++;
        }
    }
    g_cnt[n] = c;
}

// Pre-pack W_in as (w,w) u64 so phase1 w-staging is a raw 16B copy.
__global__ void pack_w(const float* __restrict__ W) {
    int i = blockIdx.x * blockDim.x + threadIdx.x;
    if (i < NIN * NRNN) { float w = W[i]; g_Wpk[i] = pack2(w, w); }
}

// Pre-pack W_out as (lo,hi) column pairs, padded to 18 pairs/row, so phase3
// w-staging is a raw 16B copy.
__global__ void pack_wout(const float* __restrict__ Wout) {
    int i = blockIdx.x * blockDim.x + threadIdx.x;
    if (i >= NRNN * 18) return;
    int k  = i / 18;
    int o2 = i - k * 18;
    float lo = (2 * o2     < NOUT) ? Wout[(size_t)k * NOUT + 2 * o2]     : 0.0f;
    float hi = (2 * o2 + 1 < NOUT) ? Wout[(size_t)k * NOUT + 2 * o2 + 1] : 0.0f;
    g_WoPk[i] = pack2(lo, hi);
}

// ---------------------------------------------------------------------------
// Kernel 0d: global transpose x[M,85] -> xT[85,M]. Shared 32x32 tile.
// ---------------------------------------------------------------------------
__global__ void transpose_x(const float* __restrict__ x) {
    __shared__ float tile[32][33];
    int mb = blockIdx.x * 32;
    int kb = blockIdx.y * 32;
    int tx = threadIdx.x;                // 32
    int ty = threadIdx.y;                // 8
    #pragma unroll
    for (int i = ty; i < 32; i += 8) {
        int k = kb + tx;
        tile[i][tx] = (k < NIN) ? x[(size_t)(mb + i) * NIN + k] : 0.0f;
    }
    __syncthreads();
    #pragma unroll
    for (int i = ty; i < 32; i += 8) {
        int k = kb + i;
        if (k < NIN) g_xT[(size_t)k * MM + mb + tx] = tile[tx][i];
    }
}

// ---------------------------------------------------------------------------
// Kernel 1: G[m,n] = x[m,:] @ W_in[:,n] + b[n] + noise[m,n]
// R10 inner loop + cp.async double-buffered staging (R12, unchanged).
// ---------------------------------------------------------------------------
#define TM 128
#define TN 64
#define KT 17
#define NTILES 5
__global__ void __launch_bounds__(128, 4) phase1_kernel(
        const float* __restrict__ bias,
        const float* __restrict__ noise) {
    __shared__ u64 As2[2][KT][TM / 2];   // row-pair a: 2 x 8.7 KB
    __shared__ u64 Wsb[2][KT][TN];       // packed w:   2 x 8.7 KB

    int tid = threadIdx.x;               // 128 threads
    int m0  = blockIdx.x * TM;           // 1000 M-tiles
    int n0  = blockIdx.y * TN;           // 8 N-tiles
    int tx  = tid & 7;
    int ty  = tid >> 3;

    u64 acc[4][8] = {};

    auto stage = [&](int buf, int k0) {
        for (int idx = tid; idx < KT * 32; idx += 128) {
            int k = idx >> 5;
            int c = idx & 31;
            cp16(s2u(&As2[buf][k][c * 2]),
                 &g_xT[(size_t)(k0 + k) * MM + m0 + c * 4]);
        }
        for (int idx = tid; idx < KT * 32; idx += 128) {
            int k = idx >> 5;
            int c = idx & 31;
            cp16(s2u(&Wsb[buf][k][c * 2]),
                 &g_Wpk[(size_t)(k0 + k) * NRNN + n0 + c * 2]);
        }
        asm volatile("cp.async.commit_group;" ::: "memory");
    };

    stage(0, 0);
    stage(1, KT);

    #pragma unroll 1
    for (int t = 0; t < NTILES; t++) {
        if (t + 1 < NTILES)
            asm volatile("cp.async.wait_group 1;" ::: "memory");
        else
            asm volatile("cp.async.wait_group 0;" ::: "memory");
        __syncthreads();

        int buf = t & 1;
        #pragma unroll
        for (int k = 0; k < KT; k++) {
            ulonglong2 a01 = *reinterpret_cast<ulonglong2*>(&As2[buf][k][ty * 4]);
            ulonglong2 a23 = *reinterpret_cast<ulonglong2*>(&As2[buf][k][ty * 4 + 2]);
            #pragma unroll
            for (int g = 0; g < 4; g++) {
                ulonglong2 w = *reinterpret_cast<ulonglong2*>(
                    &Wsb[buf][k][g * 16 + tx * 2]);
                acc[0][g*2]   = fma2(a01.x, w.x, acc[0][g*2]);
                acc[0][g*2+1] = fma2(a01.x, w.y, acc[0][g*2+1]);
                acc[1][g*2]   = fma2(a01.y, w.x, acc[1][g*2]);
                acc[1][g*2+1] = fma2(a01.y, w.y, acc[1][g*2+1]);
                acc[2][g*2]   = fma2(a23.x, w.x, acc[2][g*2]);
                acc[2][g*2+1] = fma2(a23.x, w.y, acc[2][g*2+1]);
                acc[3][g*2]   = fma2(a23.y, w.x, acc[3][g*2]);
                acc[3][g*2+1] = fma2(a23.y, w.y, acc[3][g*2+1]);
            }
        }
        __syncthreads();
        if (t + 2 < NTILES) stage(buf, (t + 2) * KT);
    }

    float2 bb[4];
    #pragma unroll
    for (int g = 0; g < 4; g++)
        bb[g] = *reinterpret_cast<const float2*>(&bias[n0 + g * 16 + tx * 2]);

    #pragma unroll
    for (int p = 0; p < 4; p++) {
        int m = m0 + ty * 8 + p * 2;
        size_t row0 = (size_t)m * NRNN + n0;
        size_t row1 = row0 + NRNN;
        #pragma unroll
        for (int g = 0; g < 4; g++) {
            int c = g * 16 + tx * 2;
            float l0, h0, l1, h1;
            unpack2(acc[p][g*2],   l0, h0);
            unpack2(acc[p][g*2+1], l1, h1);
            float2 nz0 = *reinterpret_cast<const float2*>(&noise[row0 + c]);
            float2 nz1 = *reinterpret_cast<const float2*>(&noise[row1 + c]);
            float2 o0, o1;
            o0.x = l0 + bb[g].x + nz0.x;
            o0.y = l1 + bb[g].y + nz0.y;
            o1.x = h0 + bb[g].x + nz1.x;
            o1.y = h1 + bb[g].y + nz1.y;
            *reinterpret_cast<float2*>(&g_G[row0 + c]) = o0;
            *reinterpret_cast<float2*>(&g_G[row1 + c]) = o1;
        }
    }
}

// ---------------------------------------------------------------------------
// Kernel 2a (fast path): pure-diagonal recurrence (unchanged).
// ---------------------------------------------------------------------------
__global__ void rec_diag_kernel(float* __restrict__ Hout) {
    if (!g_diag) return;
    int e = blockIdx.x * blockDim.x + threadIdx.x;   // 65536 threads
    int n = e & (NRNN - 1);
    float w = g_wdiag[n];

    const float* Gp = g_G + e;
    float*       Hp = Hout + e;

    float buf[PF];
    #pragma unroll
    for (int i = 0; i < PF; i++) buf[i] = Gp[(size_t)i * STEP];

    float h = 0.0f;
    for (int t0 = 0; t0 < TT; t0 += PF) {
        #pragma unroll
        for (int i = 0; i < PF; i++) {
            int t = t0 + i;
            float g = buf[i];
            int tf = t + PF;
            if (tf < TT) buf[i] = Gp[(size_t)tf * STEP];
            float acc = fmaf(w, h, g);
            float sp  = fmaxf(acc, 0.0f) + __logf(1.0f + __expf(-fabsf(acc)));
            h = 0.8f * h + 0.2f * sp;
            Hp[(size_t)t * STEP] = h;
        }
    }
}

// ---------------------------------------------------------------------------
// Kernel 2b (generic fallback): barriered sparse recurrence, one CTA/batch.
// ---------------------------------------------------------------------------
__global__ void rec_generic_kernel(float* __restrict__ Hout) {
    if (g_diag) return;
    __shared__ float hs[2][NRNN];
    int n = threadIdx.x;
    int b = blockIdx.x;

    hs[0][n] = 0.0f;

    int cnt = g_cnt[n];
    int   ki[4];
    float wv[4];
    #pragma unroll
    for (int j = 0; j < 4; j++) {
        if (j < cnt) { ki[j] = g_idx[n * NRNN + j]; wv[j] = g_val[n * NRNN + j]; }
        else         { ki[j] = 0;                    wv[j] = 0.0f; }
    }

    const float* Gb = g_G + (size_t)b * NRNN + n;
    float*       Hb = Hout + (size_t)b * NRNN + n;
    __syncthreads();

    int p = 0;
    float gcur = Gb[0];
    for (int t = 0; t < TT; t++) {
        int tn = (t + 1 < TT) ? (t + 1) : t;
        float gnext = Gb[(size_t)tn * STEP];

        float acc = gcur;
        acc = fmaf(wv[0], hs[p][ki[0]], acc);
        acc = fmaf(wv[1], hs[p][ki[1]], acc);
        acc = fmaf(wv[2], hs[p][ki[2]], acc);
        acc = fmaf(wv[3], hs[p][ki[3]], acc);
        for (int j = 4; j < cnt; j++)
            acc = fmaf(g_val[n * NRNN + j], hs[p][g_idx[n * NRNN + j]], acc);

        float sp = fmaxf(acc, 0.0f) + __logf(1.0f + __expf(-fabsf(acc)));
        float hn = 0.8f * hs[p][n] + 0.2f * sp;

        hs[p ^ 1][n] = hn;
        Hb[(size_t)t * STEP] = hn;
        __syncthreads();
        p ^= 1;
        gcur = gnext;
    }
}

// ---------------------------------------------------------------------------
// Kernel 3: y[m,o] = sigmoid(h[m,:] @ W_out[:,o] + b_out[o])
// cp.async DOUBLE-BUFFERED: 256 rows/CTA, 256 threads, 2 rows x 9 o2/thread.
// h staged at stride 12 floats (48B: 16B-aligned for cp.async; 4-way read
// conflicts, LSU 136 < fma 144 per epoch -> not binding). w staged from
// pre-packed g_WoPk (raw 16B copies). All 64 epochs' LDG latency hidden.
// ---------------------------------------------------------------------------
#define P3BK 8
#define P3ROWS 256
#define P3STR 12            /* 48B row stride: 16B-aligned */
#define NO2P 18             /* padded pair count */
#define NO2  17
#define NO2G 9
__global__ void __launch_bounds__(256) phase3_kernel(
        const float* __restrict__ Hin,
        const float* __restrict__ bout,
        float* __restrict__ y) {
    __shared__ __align__(16) float hsh[2][P3ROWS][P3STR];  // 24.6 KB
    __shared__ __align__(16) u64   wsh2[2][P3BK][NO2P];    // 2.3 KB

    int tid = threadIdx.x;                        // 256 threads
    int g   = tid >> 7;                           // o2 group (warp-uniform)
    int t   = tid & 127;
    int m0  = blockIdx.x * P3ROWS;                // 500 blocks
    int ob  = g * NO2G;                           // o2 base: 0 or 9

    u64 acc[2][NO2G] = {};

    auto stage = [&](int buf, int k0) {
        // h: 256 rows x 32B = 512 cp16 (dst r*48 + {0,16}: 16B-aligned)
        for (int idx = tid; idx < P3ROWS * 2; idx += 256) {
            int r    = idx >> 1;
            int half = idx & 1;
            cp16(s2u(&hsh[buf][r][half * 4]),
                 &Hin[(size_t)(m0 + r) * NRNN + k0 + half * 4]);
        }
        // w: 8k x 18 u64 = 72 cp16 from pre-packed table
        for (int idx = tid; idx < P3BK * (NO2P / 2); idx += 256) {
            int k = idx / 9;
            int c = idx - k * 9;
            cp16(s2u(&wsh2[buf][k][c * 2]),
                 &g_WoPk[(size_t)(k0 + k) * NO2P + c * 2]);
        }
        asm volatile("cp.async.commit_group;" ::: "memory");
    };

    stage(0, 0);

    #pragma unroll 1
    for (int e = 0; e < NRNN / P3BK; e++) {       // 64 epochs
        if (e + 1 < NRNN / P3BK) {
            stage((e + 1) & 1, (e + 1) * P3BK);
            asm volatile("cp.async.wait_group 1;" ::: "memory");
        } else {
            asm volatile("cp.async.wait_group 0;" ::: "memory");
        }
        __syncthreads();

        int buf = e & 1;
        #pragma unroll
        for (int kk = 0; kk < P3BK; kk++) {
            float h0 = hsh[buf][t][kk];
            float h1 = hsh[buf][t + 128][kk];
            u64 hp0 = pack2(h0, h0);
            u64 hp1 = pack2(h1, h1);
            #pragma unroll
            for (int j = 0; j < NO2G; j++) {
                u64 w = wsh2[buf][kk][ob + j];    // warp-broadcast
                acc[0][j] = fma2(hp0, w, acc[0][j]);
                acc[1][j] = fma2(hp1, w, acc[1][j]);
            }
        }
        __syncthreads();
    }

    #pragma unroll
    for (int j = 0; j < NO2G; j++) {
        int o2 = ob + j;
        if (o2 >= NO2) continue;
        float b0 = bout[2 * o2];
        float b1 = (2 * o2 + 1 < NOUT) ? bout[2 * o2 + 1] : 0.0f;
        #pragma unroll
        for (int i = 0; i < 2; i++) {
            int r = m0 + t + i * 128;
            float v0, v1;
            unpack2(acc[i][j], v0, v1);
            y[(size_t)r * NOUT + 2 * o2] = 1.0f / (1.0f + __expf(-(v0 + b0)));
            if (2 * o2 + 1 < NOUT)
                y[(size_t)r * NOUT + 2 * o2 + 1] = 1.0f / (1.0f + __expf(-(v1 + b1)));
        }
    }
}

// ---------------------------------------------------------------------------
// Launch. Inputs: x, W, b, W_out, b_out, noise.
// Output: [y_hat (T*B*33) | h (T*B*512)] fp32.
// ---------------------------------------------------------------------------
extern "C" void kernel_launch(void* const* d_in, const int* in_sizes, int n_in,
                              void* d_out, int out_size) {
    const float* x     = (const float*)d_in[0];
    const float* W     = (const float*)d_in[1];
    const float* b     = (const float*)d_in[2];
    const float* W_out = (const float*)d_in[3];
    const float* b_out = (const float*)d_in[4];
    const float* noise = (const float*)d_in[5];

    float* y = (float*)d_out;
    float* h = (float*)d_out + (size_t)TT * BB * NOUT;

    init_kernel<<<1, 1>>>();
    detect_diag<<<(NRNN * NRNN) / 256, 256>>>(W);
    build_csc<<<NRNN, 32>>>(W);                              // fallback only
    pack_w<<<(NIN * NRNN + 255) / 256, 256>>>(W);
    pack_wout<<<(NRNN * 18 + 255) / 256, 256>>>(W_out);
    transpose_x<<<dim3(MM / 32, (NIN + 31) / 32), dim3(32, 8)>>>(x);
    phase1_kernel<<<dim3(MM / TM, NRNN / TN), 128>>>(b, noise);
    rec_diag_kernel<<<(BB * NRNN) / 256, 256>>>(h);          // fast path
    rec_generic_kernel<<<BB, NRNN>>>(h);                     // fallback
    phase3_kernel<<<MM / P3ROWS, 256>>>(h, b_out, y);
}

// round 14
// speedup vs baseline: 1.4462x; 1.0477x over previous
#include <cuda_runtime.h>
#include <math.h>

#define TT    1000
#define BB    128
#define NIN   85
#define NRNN  512
#define NOUT  33
#define MM    (TT * BB)     /* 128000 rows */
#define STEP  (BB * NRNN)   /* 65536 */
#define PF    8             /* G prefetch ring depth in diag recurrence */

typedef unsigned long long u64;

// ---------------------------------------------------------------------------
// Packed f32x2 helpers (exact IEEE fp32 per lane; 2x FFMA rate on sm_103a)
// ---------------------------------------------------------------------------
__device__ __forceinline__ u64 pack2(float lo, float hi) {
    u64 r; asm("mov.b64 %0, {%1, %2};" : "=l"(r) : "f"(lo), "f"(hi)); return r;
}
__device__ __forceinline__ void unpack2(u64 v, float& lo, float& hi) {
    asm("mov.b64 {%0, %1}, %2;" : "=f"(lo), "=f"(hi) : "l"(v));
}
__device__ __forceinline__ u64 fma2(u64 a, u64 b, u64 c) {
    u64 d; asm("fma.rn.f32x2 %0, %1, %2, %3;" : "=l"(d) : "l"(a), "l"(b), "l"(c));
    return d;
}
__device__ __forceinline__ unsigned s2u(const void* p) {
    return (unsigned)__cvta_generic_to_shared(p);
}
__device__ __forceinline__ void cp16(unsigned s, const void* g) {
    asm volatile("cp.async.cg.shared.global [%0], [%1], 16;" :: "r"(s), "l"(g));
}

// ---------------------------------------------------------------------------
// Scratch (__device__ globals: module-load allocated, no runtime alloc)
// ---------------------------------------------------------------------------
__device__ float g_G[(size_t)TT * BB * NRNN];      // pre-gate, 262 MB
__device__ float g_xT[(size_t)NIN * MM];           // transposed x, 43.5 MB
__device__ __align__(16) u64 g_Wpk[(size_t)NIN * NRNN];     // (w,w) W_in
__device__ __align__(16) u64 g_WoPk[(size_t)NRNN * 18];     // (lo,hi) W_out pairs
__device__ int   g_cnt[NRNN];                      // sparse W_rec (fallback only)
__device__ int   g_idx[NRNN * NRNN];
__device__ float g_val[NRNN * NRNN];
__device__ int   g_diag = 1;   // static init; cleared only by non-diag inputs
                               // (deterministic across graph replays either way)
__device__ float g_wdiag[NRNN];                    // diagonal weight per column

// ---------------------------------------------------------------------------
// Merged prep: diag detection + W_in pack + W_out pack in ONE launch.
// Skipping exact zeros is bit-exact in fp32.
// ---------------------------------------------------------------------------
__global__ void prep_all(const float* __restrict__ W,
                         const float* __restrict__ Wout) {
    int i = blockIdx.x * blockDim.x + threadIdx.x;   // 262144 threads
    // diag detection over W_rec (512x512, coalesced in n)
    {
        int k = i >> 9;
        int n = i & (NRNN - 1);
        float w = W[(size_t)(NIN + k) * NRNN + n];
        if (k == n)          g_wdiag[n] = w;
        else if (w != 0.0f)  atomicAnd(&g_diag, 0);
    }
    // pack W_in as (w,w)
    if (i < NIN * NRNN) { float w = W[i]; g_Wpk[i] = pack2(w, w); }
    // pack W_out as (lo,hi) pairs padded to 18/row
    if (i < NRNN * 18) {
        int k  = i / 18;
        int o2 = i - k * 18;
        float lo = (2 * o2     < NOUT) ? Wout[(size_t)k * NOUT + 2 * o2]     : 0.0f;
        float hi = (2 * o2 + 1 < NOUT) ? Wout[(size_t)k * NOUT + 2 * o2 + 1] : 0.0f;
        g_WoPk[i] = pack2(lo, hi);
    }
}

// CSC build — only runs on non-diagonal inputs (predicated on !g_diag).
__global__ void build_csc(const float* __restrict__ W) {
    if (g_diag) return;
    if (threadIdx.x != 0) return;
    int n = blockIdx.x;
    int c = 0;
    for (int k = 0; k < NRNN; k++) {
        float w = W[(size_t)(NIN + k) * NRNN + n];
        if (w != 0.0f) {
            g_idx[n * NRNN + c] = k;
            g_val[n * NRNN + c] = w;
            c++;
        }
    }
    g_cnt[n] = c;
}

// ---------------------------------------------------------------------------
// Kernel 0d: global transpose x[M,85] -> xT[85,M]. Shared 32x32 tile.
// ---------------------------------------------------------------------------
__global__ void transpose_x(const float* __restrict__ x) {
    __shared__ float tile[32][33];
    int mb = blockIdx.x * 32;
    int kb = blockIdx.y * 32;
    int tx = threadIdx.x;                // 32
    int ty = threadIdx.y;                // 8
    #pragma unroll
    for (int i = ty; i < 32; i += 8) {
        int k = kb + tx;
        tile[i][tx] = (k < NIN) ? x[(size_t)(mb + i) * NIN + k] : 0.0f;
    }
    __syncthreads();
    #pragma unroll
    for (int i = ty; i < 32; i += 8) {
        int k = kb + i;
        if (k < NIN) g_xT[(size_t)k * MM + mb + tx] = tile[tx][i];
    }
}

// ---------------------------------------------------------------------------
// Kernel 1: G[m,n] = x[m,:] @ W_in[:,n] + b[n] + noise[m,n]
// R10 inner loop + cp.async double-buffered staging (R12, unchanged).
// ---------------------------------------------------------------------------
#define TM 128
#define TN 64
#define KT 17
#define NTILES 5
__global__ void __launch_bounds__(128, 4) phase1_kernel(
        const float* __restrict__ bias,
        const float* __restrict__ noise) {
    __shared__ u64 As2[2][KT][TM / 2];   // row-pair a: 2 x 8.7 KB
    __shared__ u64 Wsb[2][KT][TN];       // packed w:   2 x 8.7 KB

    int tid = threadIdx.x;               // 128 threads
    int m0  = blockIdx.x * TM;           // 1000 M-tiles
    int n0  = blockIdx.y * TN;           // 8 N-tiles
    int tx  = tid & 7;
    int ty  = tid >> 3;

    u64 acc[4][8] = {};

    auto stage = [&](int buf, int k0) {
        for (int idx = tid; idx < KT * 32; idx += 128) {
            int k = idx >> 5;
            int c = idx & 31;
            cp16(s2u(&As2[buf][k][c * 2]),
                 &g_xT[(size_t)(k0 + k) * MM + m0 + c * 4]);
        }
        for (int idx = tid; idx < KT * 32; idx += 128) {
            int k = idx >> 5;
            int c = idx & 31;
            cp16(s2u(&Wsb[buf][k][c * 2]),
                 &g_Wpk[(size_t)(k0 + k) * NRNN + n0 + c * 2]);
        }
        asm volatile("cp.async.commit_group;" ::: "memory");
    };

    stage(0, 0);
    stage(1, KT);

    #pragma unroll 1
    for (int t = 0; t < NTILES; t++) {
        if (t + 1 < NTILES)
            asm volatile("cp.async.wait_group 1;" ::: "memory");
        else
            asm volatile("cp.async.wait_group 0;" ::: "memory");
        __syncthreads();

        int buf = t & 1;
        #pragma unroll
        for (int k = 0; k < KT; k++) {
            ulonglong2 a01 = *reinterpret_cast<ulonglong2*>(&As2[buf][k][ty * 4]);
            ulonglong2 a23 = *reinterpret_cast<ulonglong2*>(&As2[buf][k][ty * 4 + 2]);
            #pragma unroll
            for (int g = 0; g < 4; g++) {
                ulonglong2 w = *reinterpret_cast<ulonglong2*>(
                    &Wsb[buf][k][g * 16 + tx * 2]);
                acc[0][g*2]   = fma2(a01.x, w.x, acc[0][g*2]);
                acc[0][g*2+1] = fma2(a01.x, w.y, acc[0][g*2+1]);
                acc[1][g*2]   = fma2(a01.y, w.x, acc[1][g*2]);
                acc[1][g*2+1] = fma2(a01.y, w.y, acc[1][g*2+1]);
                acc[2][g*2]   = fma2(a23.x, w.x, acc[2][g*2]);
                acc[2][g*2+1] = fma2(a23.x, w.y, acc[2][g*2+1]);
                acc[3][g*2]   = fma2(a23.y, w.x, acc[3][g*2]);
                acc[3][g*2+1] = fma2(a23.y, w.y, acc[3][g*2+1]);
            }
        }
        __syncthreads();
        if (t + 2 < NTILES) stage(buf, (t + 2) * KT);
    }

    float2 bb[4];
    #pragma unroll
    for (int g = 0; g < 4; g++)
        bb[g] = *reinterpret_cast<const float2*>(&bias[n0 + g * 16 + tx * 2]);

    #pragma unroll
    for (int p = 0; p < 4; p++) {
        int m = m0 + ty * 8 + p * 2;
        size_t row0 = (size_t)m * NRNN + n0;
        size_t row1 = row0 + NRNN;
        #pragma unroll
        for (int g = 0; g < 4; g++) {
            int c = g * 16 + tx * 2;
            float l0, h0, l1, h1;
            unpack2(acc[p][g*2],   l0, h0);
            unpack2(acc[p][g*2+1], l1, h1);
            float2 nz0 = *reinterpret_cast<const float2*>(&noise[row0 + c]);
            float2 nz1 = *reinterpret_cast<const float2*>(&noise[row1 + c]);
            float2 o0, o1;
            o0.x = l0 + bb[g].x + nz0.x;
            o0.y = l1 + bb[g].y + nz0.y;
            o1.x = h0 + bb[g].x + nz1.x;
            o1.y = h1 + bb[g].y + nz1.y;
            *reinterpret_cast<float2*>(&g_G[row0 + c]) = o0;
            *reinterpret_cast<float2*>(&g_G[row1 + c]) = o1;
        }
    }
}

// ---------------------------------------------------------------------------
// Kernel 2a (fast path): pure-diagonal recurrence (unchanged).
// ---------------------------------------------------------------------------
__global__ void rec_diag_kernel(float* __restrict__ Hout) {
    if (!g_diag) return;
    int e = blockIdx.x * blockDim.x + threadIdx.x;   // 65536 threads
    int n = e & (NRNN - 1);
    float w = g_wdiag[n];

    const float* Gp = g_G + e;
    float*       Hp = Hout + e;

    float buf[PF];
    #pragma unroll
    for (int i = 0; i < PF; i++) buf[i] = Gp[(size_t)i * STEP];

    float h = 0.0f;
    for (int t0 = 0; t0 < TT; t0 += PF) {
        #pragma unroll
        for (int i = 0; i < PF; i++) {
            int t = t0 + i;
            float g = buf[i];
            int tf = t + PF;
            if (tf < TT) buf[i] = Gp[(size_t)tf * STEP];
            float acc = fmaf(w, h, g);
            float sp  = fmaxf(acc, 0.0f) + __logf(1.0f + __expf(-fabsf(acc)));
            h = 0.8f * h + 0.2f * sp;
            Hp[(size_t)t * STEP] = h;
        }
    }
}

// ---------------------------------------------------------------------------
// Kernel 2b (generic fallback): barriered sparse recurrence, one CTA/batch.
// ---------------------------------------------------------------------------
__global__ void rec_generic_kernel(float* __restrict__ Hout) {
    if (g_diag) return;
    __shared__ float hs[2][NRNN];
    int n = threadIdx.x;
    int b = blockIdx.x;

    hs[0][n] = 0.0f;

    int cnt = g_cnt[n];
    int   ki[4];
    float wv[4];
    #pragma unroll
    for (int j = 0; j < 4; j++) {
        if (j < cnt) { ki[j] = g_idx[n * NRNN + j]; wv[j] = g_val[n * NRNN + j]; }
        else         { ki[j] = 0;                    wv[j] = 0.0f; }
    }

    const float* Gb = g_G + (size_t)b * NRNN + n;
    float*       Hb = Hout + (size_t)b * NRNN + n;
    __syncthreads();

    int p = 0;
    float gcur = Gb[0];
    for (int t = 0; t < TT; t++) {
        int tn = (t + 1 < TT) ? (t + 1) : t;
        float gnext = Gb[(size_t)tn * STEP];

        float acc = gcur;
        acc = fmaf(wv[0], hs[p][ki[0]], acc);
        acc = fmaf(wv[1], hs[p][ki[1]], acc);
        acc = fmaf(wv[2], hs[p][ki[2]], acc);
        acc = fmaf(wv[3], hs[p][ki[3]], acc);
        for (int j = 4; j < cnt; j++)
            acc = fmaf(g_val[n * NRNN + j], hs[p][g_idx[n * NRNN + j]], acc);

        float sp = fmaxf(acc, 0.0f) + __logf(1.0f + __expf(-fabsf(acc)));
        float hn = 0.8f * hs[p][n] + 0.2f * sp;

        hs[p ^ 1][n] = hn;
        Hb[(size_t)t * STEP] = hn;
        __syncthreads();
        p ^= 1;
        gcur = gnext;
    }
}

// ---------------------------------------------------------------------------
// Kernel 3: y[m,o] = sigmoid(h[m,:] @ W_out[:,o] + b_out[o])
// cp.async double-buffered; P3BK=16: per-row staging is 64B contiguous
// (full DRAM sectors, was 32B = 50% sector waste) and 32 epochs (was 64).
// h stride 20 floats (80B: 16B-aligned; 4-way read conflicts, not binding).
// ---------------------------------------------------------------------------
#define P3BK 16
#define P3ROWS 256
#define P3STR 20            /* 80B row stride: 16B-aligned */
#define NO2P 18             /* padded pair count */
#define NO2  17
#define NO2G 9
__global__ void __launch_bounds__(256) phase3_kernel(
        const float* __restrict__ Hin,
        const float* __restrict__ bout,
        float* __restrict__ y) {
    __shared__ __align__(16) float hsh[2][P3ROWS][P3STR];  // 40 KB
    __shared__ __align__(16) u64   wsh2[2][P3BK][NO2P];    // 4.6 KB

    int tid = threadIdx.x;                        // 256 threads
    int g   = tid >> 7;                           // o2 group (warp-uniform)
    int t   = tid & 127;
    int m0  = blockIdx.x * P3ROWS;                // 500 blocks
    int ob  = g * NO2G;                           // o2 base: 0 or 9

    u64 acc[2][NO2G] = {};

    auto stage = [&](int buf, int k0) {
        // h: 256 rows x 64B = 1024 cp16, 64B contiguous per row
        for (int idx = tid; idx < P3ROWS * 4; idx += 256) {
            int r = idx >> 2;
            int q = idx & 3;
            cp16(s2u(&hsh[buf][r][q * 4]),
                 &Hin[(size_t)(m0 + r) * NRNN + k0 + q * 4]);
        }
        // w: 16k x 18 u64 = 144 cp16 from pre-packed table
        for (int idx = tid; idx < P3BK * (NO2P / 2); idx += 256) {
            int k = idx / 9;
            int c = idx - k * 9;
            cp16(s2u(&wsh2[buf][k][c * 2]),
                 &g_WoPk[(size_t)(k0 + k) * NO2P + c * 2]);
        }
        asm volatile("cp.async.commit_group;" ::: "memory");
    };

    stage(0, 0);

    #pragma unroll 1
    for (int e = 0; e < NRNN / P3BK; e++) {       // 32 epochs
        if (e + 1 < NRNN / P3BK) {
            stage((e + 1) & 1, (e + 1) * P3BK);
            asm volatile("cp.async.wait_group 1;" ::: "memory");
        } else {
            asm volatile("cp.async.wait_group 0;" ::: "memory");
        }
        __syncthreads();

        int buf = e & 1;
        #pragma unroll
        for (int kk = 0; kk < P3BK; kk++) {
            float h0 = hsh[buf][t][kk];
            float h1 = hsh[buf][t + 128][kk];
            u64 hp0 = pack2(h0, h0);
            u64 hp1 = pack2(h1, h1);
            #pragma unroll
            for (int j = 0; j < NO2G; j++) {
                u64 w = wsh2[buf][kk][ob + j];    // warp-broadcast
                acc[0][j] = fma2(hp0, w, acc[0][j]);
                acc[1][j] = fma2(hp1, w, acc[1][j]);
            }
        }
        __syncthreads();
    }

    #pragma unroll
    for (int j = 0; j < NO2G; j++) {
        int o2 = ob + j;
        if (o2 >= NO2) continue;
        float b0 = bout[2 * o2];
        float b1 = (2 * o2 + 1 < NOUT) ? bout[2 * o2 + 1] : 0.0f;
        #pragma unroll
        for (int i = 0; i < 2; i++) {
            int r = m0 + t + i * 128;
            float v0, v1;
            unpack2(acc[i][j], v0, v1);
            y[(size_t)r * NOUT + 2 * o2] = 1.0f / (1.0f + __expf(-(v0 + b0)));
            if (2 * o2 + 1 < NOUT)
                y[(size_t)r * NOUT + 2 * o2 + 1] = 1.0f / (1.0f + __expf(-(v1 + b1)));
        }
    }
}

// ---------------------------------------------------------------------------
// Launch. Inputs: x, W, b, W_out, b_out, noise.
// Output: [y_hat (T*B*33) | h (T*B*512)] fp32.
// ---------------------------------------------------------------------------
extern "C" void kernel_launch(void* const* d_in, const int* in_sizes, int n_in,
                              void* d_out, int out_size) {
    const float* x     = (const float*)d_in[0];
    const float* W     = (const float*)d_in[1];
    const float* b     = (const float*)d_in[2];
    const float* W_out = (const float*)d_in[3];
    const float* b_out = (const float*)d_in[4];
    const float* noise = (const float*)d_in[5];

    float* y = (float*)d_out;
    float* h = (float*)d_out + (size_t)TT * BB * NOUT;

    prep_all<<<(NRNN * NRNN) / 256, 256>>>(W, W_out);
    build_csc<<<NRNN, 32>>>(W);                              // fallback only
    transpose_x<<<dim3(MM / 32, (NIN + 31) / 32), dim3(32, 8)>>>(x);
    phase1_kernel<<<dim3(MM / TM, NRNN / TN), 128>>>(b, noise);
    rec_diag_kernel<<<(BB * NRNN) / 256, 256>>>(h);          // fast path
    rec_generic_kernel<<<BB, NRNN>>>(h);                     // fallback
    phase3_kernel<<<MM / P3ROWS, 256>>>(h, b_out, y);
}

// round 16
// speedup vs baseline: 1.5583x; 1.0775x over previous
#include <cuda_runtime.h>
#include <math.h>

#define TT    1000
#define BB    128
#define NIN   85
#define NRNN  512
#define NOUT  33
#define MM    (TT * BB)     /* 128000 rows */
#define STEP  (BB * NRNN)   /* 65536 */
#define PF    20            /* G prefetch ring depth; MUST divide TT=1000 */

typedef unsigned long long u64;

// ---------------------------------------------------------------------------
// Packed f32x2 helpers (exact IEEE fp32 per lane; 2x FFMA rate on sm_103a)
// ---------------------------------------------------------------------------
__device__ __forceinline__ u64 pack2(float lo, float hi) {
    u64 r; asm("mov.b64 %0, {%1, %2};" : "=l"(r) : "f"(lo), "f"(hi)); return r;
}
__device__ __forceinline__ void unpack2(u64 v, float& lo, float& hi) {
    asm("mov.b64 {%0, %1}, %2;" : "=f"(lo), "=f"(hi) : "l"(v));
}
__device__ __forceinline__ u64 fma2(u64 a, u64 b, u64 c) {
    u64 d; asm("fma.rn.f32x2 %0, %1, %2, %3;" : "=l"(d) : "l"(a), "l"(b), "l"(c));
    return d;
}
__device__ __forceinline__ unsigned s2u(const void* p) {
    return (unsigned)__cvta_generic_to_shared(p);
}
__device__ __forceinline__ void cp16(unsigned s, const void* g) {
    asm volatile("cp.async.cg.shared.global [%0], [%1], 16;" :: "r"(s), "l"(g));
}

// ---------------------------------------------------------------------------
// Scratch (__device__ globals: module-load allocated, no runtime alloc)
// ---------------------------------------------------------------------------
__device__ float g_G[(size_t)TT * BB * NRNN];      // pre-gate, 262 MB
__device__ __align__(16) float g_xT[(size_t)NIN * MM];      // transposed x
__device__ __align__(16) u64   g_WoPk[(size_t)NRNN * 18];   // (lo,hi) W_out pairs
__device__ int   g_cnt[NRNN];                      // sparse W_rec (fallback only)
__device__ int   g_idx[NRNN * NRNN];
__device__ float g_val[NRNN * NRNN];
__device__ int   g_diag = 1;   // static init; cleared only by non-diag inputs
__device__ float g_wdiag[NRNN];                    // diagonal weight per column

// ---------------------------------------------------------------------------
// Merged prep: diag detection + W_out pack in ONE launch.
// Skipping exact zeros is bit-exact in fp32.
// ---------------------------------------------------------------------------
__global__ void prep_all(const float* __restrict__ W,
                         const float* __restrict__ Wout) {
    int i = blockIdx.x * blockDim.x + threadIdx.x;   // 262144 threads
    {
        int k = i >> 9;
        int n = i & (NRNN - 1);
        float w = W[(size_t)(NIN + k) * NRNN + n];
        if (k == n)          g_wdiag[n] = w;
        else if (w != 0.0f)  atomicAnd(&g_diag, 0);
    }
    if (i < NRNN * 18) {
        int k  = i / 18;
        int o2 = i - k * 18;
        float lo = (2 * o2     < NOUT) ? Wout[(size_t)k * NOUT + 2 * o2]     : 0.0f;
        float hi = (2 * o2 + 1 < NOUT) ? Wout[(size_t)k * NOUT + 2 * o2 + 1] : 0.0f;
        g_WoPk[i] = pack2(lo, hi);
    }
}

// CSC build — only runs on non-diagonal inputs (predicated on !g_diag).
__global__ void build_csc(const float* __restrict__ W) {
    if (g_diag) return;
    if (threadIdx.x != 0) return;
    int n = blockIdx.x;
    int c = 0;
    for (int k = 0; k < NRNN; k++) {
        float w = W[(size_t)(NIN + k) * NRNN + n];
        if (w != 0.0f) {
            g_idx[n * NRNN + c] = k;
            g_val[n * NRNN + c] = w;
            c++;
        }
    }
    g_cnt[n] = c;
}

// ---------------------------------------------------------------------------
// Kernel 0d: global transpose x[M,85] -> xT[85,M]. Shared 32x32 tile.
// Writes vectorized: each thread emits one float4 (STG.128, coalesced).
// ---------------------------------------------------------------------------
__global__ void transpose_x(const float* __restrict__ x) {
    __shared__ float tile[32][33];
    int mb  = blockIdx.x * 32;
    int kb  = blockIdx.y * 32;
    int tid = threadIdx.x;               // 256 threads
    int tx  = tid & 31;
    int ty  = tid >> 5;                  // 8
    #pragma unroll
    for (int i = ty; i < 32; i += 8) {
        int k = kb + tx;
        tile[i][tx] = (k < NIN) ? x[(size_t)(mb + i) * NIN + k] : 0.0f;
    }
    __syncthreads();
    {
        int kl = tid >> 3;               // 0..31 (k within tile)
        int m4 = tid & 7;                // 0..7  (float4 group of m)
        int k  = kb + kl;
        if (k < NIN) {
            float4 v;
            v.x = tile[m4 * 4 + 0][kl];
            v.y = tile[m4 * 4 + 1][kl];
            v.z = tile[m4 * 4 + 2][kl];
            v.w = tile[m4 * 4 + 3][kl];
            *reinterpret_cast<float4*>(&g_xT[(size_t)k * MM + mb + m4 * 4]) = v;
        }
    }
}

// ---------------------------------------------------------------------------
// Kernel 1: G[m,n] = x[m,:] @ W_in[:,n] + b[n] + noise[m,n]
// 128 thr, 8 rows x 8 cols, cp.async double-buffered (KT=17, 5 tiles).
// NATURAL-PAIR w (1.0 smem B/MAC): w staged raw from W (2 LDS.128/k, was 4
// of duplicated (w,w)); a plain floats, broadcast pairs built with 8 movs/k
// in registers. Inner: 4 LDS + 8 MOV + 32 FFMA2. Contiguous float4 epilogue.
// ---------------------------------------------------------------------------
#define TM 128
#define TN 64
#define KT 17
#define NTILES 5
__global__ void __launch_bounds__(128, 4) phase1_kernel(
        const float* __restrict__ W,
        const float* __restrict__ bias,
        const float* __restrict__ noise) {
    __shared__ __align__(16) float As[2][KT][TM];      // 2 x 8.7 KB
    __shared__ __align__(16) u64   Ws[2][KT][TN / 2];  // 2 x 4.35 KB

    int tid = threadIdx.x;               // 128 threads
    int m0  = blockIdx.x * TM;           // 1000 M-tiles
    int n0  = blockIdx.y * TN;           // 8 N-tiles
    int tx  = tid & 7;                   // col group: cols tx*8..tx*8+7
    int ty  = tid >> 3;                  // row group: rows ty*8..ty*8+7

    u64 acc[8][4] = {};                  // [row][colpair]

    auto stage = [&](int buf, int k0) {
        for (int idx = tid; idx < KT * 32; idx += 128) {
            int k = idx >> 5;
            int c = idx & 31;
            cp16(s2u(&As[buf][k][c * 4]),
                 &g_xT[(size_t)(k0 + k) * MM + m0 + c * 4]);
        }
        for (int idx = tid; idx < KT * 16; idx += 128) {
            int k = idx >> 4;
            int c = idx & 15;
            cp16(s2u(&Ws[buf][k][c * 2]),
                 &W[(size_t)(k0 + k) * NRNN + n0 + c * 4]);
        }
        asm volatile("cp.async.commit_group;" ::: "memory");
    };

    stage(0, 0);
    stage(1, KT);

    #pragma unroll 1
    for (int t = 0; t < NTILES; t++) {
        if (t + 1 < NTILES)
            asm volatile("cp.async.wait_group 1;" ::: "memory");
        else
            asm volatile("cp.async.wait_group 0;" ::: "memory");
        __syncthreads();

        int buf = t & 1;
        #pragma unroll
        for (int k = 0; k < KT; k++) {
            float4 a0 = *reinterpret_cast<float4*>(&As[buf][k][ty * 8]);
            float4 a1 = *reinterpret_cast<float4*>(&As[buf][k][ty * 8 + 4]);
            ulonglong2 w01 = *reinterpret_cast<ulonglong2*>(&Ws[buf][k][tx * 4]);
            ulonglong2 w23 = *reinterpret_cast<ulonglong2*>(&Ws[buf][k][tx * 4 + 2]);
            u64 ap[8] = { pack2(a0.x, a0.x), pack2(a0.y, a0.y),
                          pack2(a0.z, a0.z), pack2(a0.w, a0.w),
                          pack2(a1.x, a1.x), pack2(a1.y, a1.y),
                          pack2(a1.z, a1.z), pack2(a1.w, a1.w) };
            #pragma unroll
            for (int r = 0; r < 8; r++) {
                acc[r][0] = fma2(ap[r], w01.x, acc[r][0]);
                acc[r][1] = fma2(ap[r], w01.y, acc[r][1]);
                acc[r][2] = fma2(ap[r], w23.x, acc[r][2]);
                acc[r][3] = fma2(ap[r], w23.y, acc[r][3]);
            }
        }
        __syncthreads();
        if (t + 2 < NTILES) stage(buf, (t + 2) * KT);
    }

    // epilogue: acc[r][cp] = row (ty*8+r), cols n0+tx*8+2cp..+2cp+1 (contig)
    float4 bb0 = *reinterpret_cast<const float4*>(&bias[n0 + tx * 8]);
    float4 bb1 = *reinterpret_cast<const float4*>(&bias[n0 + tx * 8 + 4]);

    #pragma unroll
    for (int r = 0; r < 8; r++) {
        int m = m0 + ty * 8 + r;
        size_t off = (size_t)m * NRNN + n0 + tx * 8;
        float4 nz0 = *reinterpret_cast<const float4*>(&noise[off]);
        float4 nz1 = *reinterpret_cast<const float4*>(&noise[off + 4]);
        float v0, v1, v2, v3, v4, v5, v6, v7;
        unpack2(acc[r][0], v0, v1);
        unpack2(acc[r][1], v2, v3);
        unpack2(acc[r][2], v4, v5);
        unpack2(acc[r][3], v6, v7);
        float4 o0, o1;
        o0.x = v0 + bb0.x + nz0.x;  o0.y = v1 + bb0.y + nz0.y;
        o0.z = v2 + bb0.z + nz0.z;  o0.w = v3 + bb0.w + nz0.w;
        o1.x = v4 + bb1.x + nz1.x;  o1.y = v5 + bb1.y + nz1.y;
        o1.z = v6 + bb1.z + nz1.z;  o1.w = v7 + bb1.w + nz1.w;
        *reinterpret_cast<float4*>(&g_G[off])     = o0;
        *reinterpret_cast<float4*>(&g_G[off + 4]) = o1;
    }
}

// ---------------------------------------------------------------------------
// Kernel 2a (fast path): pure-diagonal recurrence. PF=20 prefetch ring
// (divides TT=1000; ~700 cyc coverage > DRAM latency).
// ---------------------------------------------------------------------------
__global__ void rec_diag_kernel(float* __restrict__ Hout) {
    if (!g_diag) return;
    int e = blockIdx.x * blockDim.x + threadIdx.x;   // 65536 threads
    int n = e & (NRNN - 1);
    float w = g_wdiag[n];

    const float* Gp = g_G + e;
    float*       Hp = Hout + e;

    float buf[PF];
    #pragma unroll
    for (int i = 0; i < PF; i++) buf[i] = Gp[(size_t)i * STEP];

    float h = 0.0f;
    for (int t0 = 0; t0 < TT; t0 += PF) {            // 50 iterations exactly
        #pragma unroll
        for (int i = 0; i < PF; i++) {
            int t = t0 + i;
            float g = buf[i];
            int tf = t + PF;
            if (tf < TT) buf[i] = Gp[(size_t)tf * STEP];
            float acc = fmaf(w, h, g);
            float sp  = fmaxf(acc, 0.0f) + __logf(1.0f + __expf(-fabsf(acc)));
            h = 0.8f * h + 0.2f * sp;
            Hp[(size_t)t * STEP] = h;
        }
    }
}

// ---------------------------------------------------------------------------
// Kernel 2b (generic fallback): barriered sparse recurrence, one CTA/batch.
// ---------------------------------------------------------------------------
__global__ void rec_generic_kernel(float* __restrict__ Hout) {
    if (g_diag) return;
    __shared__ float hs[2][NRNN];
    int n = threadIdx.x;
    int b = blockIdx.x;

    hs[0][n] = 0.0f;

    int cnt = g_cnt[n];
    int   ki[4];
    float wv[4];
    #pragma unroll
    for (int j = 0; j < 4; j++) {
        if (j < cnt) { ki[j] = g_idx[n * NRNN + j]; wv[j] = g_val[n * NRNN + j]; }
        else         { ki[j] = 0;                    wv[j] = 0.0f; }
    }

    const float* Gb = g_G + (size_t)b * NRNN + n;
    float*       Hb = Hout + (size_t)b * NRNN + n;
    __syncthreads();

    int p = 0;
    float gcur = Gb[0];
    for (int t = 0; t < TT; t++) {
        int tn = (t + 1 < TT) ? (t + 1) : t;
        float gnext = Gb[(size_t)tn * STEP];

        float acc = gcur;
        acc = fmaf(wv[0], hs[p][ki[0]], acc);
        acc = fmaf(wv[1], hs[p][ki[1]], acc);
        acc = fmaf(wv[2], hs[p][ki[2]], acc);
        acc = fmaf(wv[3], hs[p][ki[3]], acc);
        for (int j = 4; j < cnt; j++)
            acc = fmaf(g_val[n * NRNN + j], hs[p][g_idx[n * NRNN + j]], acc);

        float sp = fmaxf(acc, 0.0f) + __logf(1.0f + __expf(-fabsf(acc)));
        float hn = 0.8f * hs[p][n] + 0.2f * sp;

        hs[p ^ 1][n] = hn;
        Hb[(size_t)t * STEP] = hn;
        __syncthreads();
        p ^= 1;
        gcur = gnext;
    }
}

// ---------------------------------------------------------------------------
// Kernel 3: y[m,o] = sigmoid(h[m,:] @ W_out[:,o] + b_out[o])
// cp.async double-buffered, P3BK=16 (R14, unchanged).
// ---------------------------------------------------------------------------
#define P3BK 16
#define P3ROWS 256
#define P3STR 20            /* 80B row stride: 16B-aligned */
#define NO2P 18
#define NO2  17
#define NO2G 9
__global__ void __launch_bounds__(256) phase3_kernel(
        const float* __restrict__ Hin,
        const float* __restrict__ bout,
        float* __restrict__ y) {
    __shared__ __align__(16) float hsh[2][P3ROWS][P3STR];  // 40 KB
    __shared__ __align__(16) u64   wsh2[2][P3BK][NO2P];    // 4.6 KB

    int tid = threadIdx.x;                        // 256 threads
    int g   = tid >> 7;
    int t   = tid & 127;
    int m0  = blockIdx.x * P3ROWS;                // 500 blocks
    int ob  = g * NO2G;

    u64 acc[2][NO2G] = {};

    auto stage = [&](int buf, int k0) {
        for (int idx = tid; idx < P3ROWS * 4; idx += 256) {
            int r = idx >> 2;
            int q = idx & 3;
            cp16(s2u(&hsh[buf][r][q * 4]),
                 &Hin[(size_t)(m0 + r) * NRNN + k0 + q * 4]);
        }
        for (int idx = tid; idx < P3BK * (NO2P / 2); idx += 256) {
            int k = idx / 9;
            int c = idx - k * 9;
            cp16(s2u(&wsh2[buf][k][c * 2]),
                 &g_WoPk[(size_t)(k0 + k) * NO2P + c * 2]);
        }
        asm volatile("cp.async.commit_group;" ::: "memory");
    };

    stage(0, 0);

    #pragma unroll 1
    for (int e = 0; e < NRNN / P3BK; e++) {       // 32 epochs
        if (e + 1 < NRNN / P3BK) {
            stage((e + 1) & 1, (e + 1) * P3BK);
            asm volatile("cp.async.wait_group 1;" ::: "memory");
        } else {
            asm volatile("cp.async.wait_group 0;" ::: "memory");
        }
        __syncthreads();

        int buf = e & 1;
        #pragma unroll
        for (int kk = 0; kk < P3BK; kk++) {
            float h0 = hsh[buf][t][kk];
            float h1 = hsh[buf][t + 128][kk];
            u64 hp0 = pack2(h0, h0);
            u64 hp1 = pack2(h1, h1);
            #pragma unroll
            for (int j = 0; j < NO2G; j++) {
                u64 w = wsh2[buf][kk][ob + j];
                acc[0][j] = fma2(hp0, w, acc[0][j]);
                acc[1][j] = fma2(hp1, w, acc[1][j]);
            }
        }
        __syncthreads();
    }

    #pragma unroll
    for (int j = 0; j < NO2G; j++) {
        int o2 = ob + j;
        if (o2 >= NO2) continue;
        float b0 = bout[2 * o2];
        float b1 = (2 * o2 + 1 < NOUT) ? bout[2 * o2 + 1] : 0.0f;
        #pragma unroll
        for (int i = 0; i < 2; i++) {
            int r = m0 + t + i * 128;
            float v0, v1;
            unpack2(acc[i][j], v0, v1);
            y[(size_t)r * NOUT + 2 * o2] = 1.0f / (1.0f + __expf(-(v0 + b0)));
            if (2 * o2 + 1 < NOUT)
                y[(size_t)r * NOUT + 2 * o2 + 1] = 1.0f / (1.0f + __expf(-(v1 + b1)));
        }
    }
}

// ---------------------------------------------------------------------------
// Launch. Inputs: x, W, b, W_out, b_out, noise.
// Output: [y_hat (T*B*33) | h (T*B*512)] fp32.
// ---------------------------------------------------------------------------
extern "C" void kernel_launch(void* const* d_in, const int* in_sizes, int n_in,
                              void* d_out, int out_size) {
    const float* x     = (const float*)d_in[0];
    const float* W     = (const float*)d_in[1];
    const float* b     = (const float*)d_in[2];
    const float* W_out = (const float*)d_in[3];
    const float* b_out = (const float*)d_in[4];
    const float* noise = (const float*)d_in[5];

    float* y = (float*)d_out;
    float* h = (float*)d_out + (size_t)TT * BB * NOUT;

    prep_all<<<(NRNN * NRNN) / 256, 256>>>(W, W_out);
    build_csc<<<NRNN, 32>>>(W);                              // fallback only
    transpose_x<<<dim3(MM / 32, (NIN + 31) / 32), 256>>>(x);
    phase1_kernel<<<dim3(MM / TM, NRNN / TN), 128>>>(W, b, noise);
    rec_diag_kernel<<<(BB * NRNN) / 256, 256>>>(h);          // fast path
    rec_generic_kernel<<<BB, NRNN>>>(h);                     // fallback
    phase3_kernel<<<MM / P3ROWS, 256>>>(h, b_out, y);
}